// round 10
// baseline (speedup 1.0000x reference)
#include <cuda_runtime.h>
#include <cuda_bf16.h>
#include <math.h>
#include <stdint.h>

// Problem shapes (fixed)
#define BB 64
#define TT 512
#define DD 1024
#define UU 128
#define MM (BB * TT)

typedef unsigned long long u64;

// Scratch (no cudaMalloc allowed)
__device__ float g_logits[MM * UU];   // GEMM output
__device__ float g_hist[MM * UU];     // viterbi state history (t>=1)

// ---------------------------------------------------------------------------
// Kernel 1: logits = X(M,K) @ W(K,U) + bias  (exact fp32, double-buffered)
// ---------------------------------------------------------------------------
#define GBM 128
#define GBK 16

__global__ __launch_bounds__(256, 2)
void gemm_bias_kernel(const float* __restrict__ A,
                      const float* __restrict__ W,
                      const float* __restrict__ bias)
{
    __shared__ float As[2][GBK][GBM];
    __shared__ float Bs[2][GBK][UU];

    const int tid  = threadIdx.x;
    const int row0 = blockIdx.x * GBM;

    const int arow = tid >> 2;
    const int ak   = (tid & 3) * 4;
    const int wk   = tid >> 5;
    const int wcol = (tid & 31) * 4;

    const int tx = tid & 15;
    const int ty = tid >> 4;

    float acc[8][8];
    #pragma unroll
    for (int i = 0; i < 8; i++)
        #pragma unroll
        for (int j = 0; j < 8; j++)
            acc[i][j] = 0.0f;

    const float* A0 = A + (size_t)(row0 + arow) * DD + ak;
    const float* A1 = A + (size_t)(row0 + arow + 64) * DD + ak;

    float4 ra0 = *reinterpret_cast<const float4*>(A0);
    float4 ra1 = *reinterpret_cast<const float4*>(A1);
    float4 rw0 = *reinterpret_cast<const float4*>(&W[(size_t)wk * UU + wcol]);
    float4 rw1 = *reinterpret_cast<const float4*>(&W[(size_t)(wk + 8) * UU + wcol]);

    As[0][ak + 0][arow] = ra0.x; As[0][ak + 1][arow] = ra0.y;
    As[0][ak + 2][arow] = ra0.z; As[0][ak + 3][arow] = ra0.w;
    As[0][ak + 0][arow + 64] = ra1.x; As[0][ak + 1][arow + 64] = ra1.y;
    As[0][ak + 2][arow + 64] = ra1.z; As[0][ak + 3][arow + 64] = ra1.w;
    *reinterpret_cast<float4*>(&Bs[0][wk][wcol])     = rw0;
    *reinterpret_cast<float4*>(&Bs[0][wk + 8][wcol]) = rw1;
    __syncthreads();

    int st = 0;
    for (int k0 = GBK; k0 <= DD; k0 += GBK) {
        const bool more = (k0 < DD);
        if (more) {
            ra0 = *reinterpret_cast<const float4*>(A0 + k0);
            ra1 = *reinterpret_cast<const float4*>(A1 + k0);
            rw0 = *reinterpret_cast<const float4*>(&W[(size_t)(k0 + wk) * UU + wcol]);
            rw1 = *reinterpret_cast<const float4*>(&W[(size_t)(k0 + wk + 8) * UU + wcol]);
        }

        #pragma unroll
        for (int k = 0; k < GBK; k++) {
            float a[8], b[8];
            *reinterpret_cast<float4*>(&a[0]) =
                *reinterpret_cast<const float4*>(&As[st][k][ty * 8]);
            *reinterpret_cast<float4*>(&a[4]) =
                *reinterpret_cast<const float4*>(&As[st][k][ty * 8 + 4]);
            *reinterpret_cast<float4*>(&b[0]) =
                *reinterpret_cast<const float4*>(&Bs[st][k][tx * 8]);
            *reinterpret_cast<float4*>(&b[4]) =
                *reinterpret_cast<const float4*>(&Bs[st][k][tx * 8 + 4]);
            #pragma unroll
            for (int i = 0; i < 8; i++)
                #pragma unroll
                for (int j = 0; j < 8; j++)
                    acc[i][j] = fmaf(a[i], b[j], acc[i][j]);
        }

        if (more) {
            const int ns = st ^ 1;
            As[ns][ak + 0][arow] = ra0.x; As[ns][ak + 1][arow] = ra0.y;
            As[ns][ak + 2][arow] = ra0.z; As[ns][ak + 3][arow] = ra0.w;
            As[ns][ak + 0][arow + 64] = ra1.x; As[ns][ak + 1][arow + 64] = ra1.y;
            As[ns][ak + 2][arow + 64] = ra1.z; As[ns][ak + 3][arow + 64] = ra1.w;
            *reinterpret_cast<float4*>(&Bs[ns][wk][wcol])     = rw0;
            *reinterpret_cast<float4*>(&Bs[ns][wk + 8][wcol]) = rw1;
            __syncthreads();
            st = ns;
        }
    }

    float bv[8];
    *reinterpret_cast<float4*>(&bv[0]) =
        *reinterpret_cast<const float4*>(&bias[tx * 8]);
    *reinterpret_cast<float4*>(&bv[4]) =
        *reinterpret_cast<const float4*>(&bias[tx * 8 + 4]);

    #pragma unroll
    for (int i = 0; i < 8; i++) {
        const size_t row = (size_t)(row0 + ty * 8 + i);
        float4 o0, o1;
        o0.x = acc[i][0] + bv[0]; o0.y = acc[i][1] + bv[1];
        o0.z = acc[i][2] + bv[2]; o0.w = acc[i][3] + bv[3];
        o1.x = acc[i][4] + bv[4]; o1.y = acc[i][5] + bv[5];
        o1.z = acc[i][6] + bv[6]; o1.w = acc[i][7] + bv[7];
        *reinterpret_cast<float4*>(&g_logits[row * UU + tx * 8])     = o0;
        *reinterpret_cast<float4*>(&g_logits[row * UU + tx * 8 + 4]) = o1;
    }
}

// ---------------------------------------------------------------------------
// ordered-int argmax helpers (exact, first-index tie rule)
// ---------------------------------------------------------------------------
__device__ __forceinline__ unsigned fkey(float f)
{
    const unsigned b = __float_as_uint(f);
    return b ^ ((unsigned)(((int)b) >> 31) | 0x80000000u);
}
__device__ __forceinline__ unsigned redux_max_u32(unsigned v)
{
    unsigned r;
    asm("redux.sync.max.u32 %0, %1, 0xffffffff;" : "=r"(r) : "r"(v));
    return r;
}
__device__ __forceinline__ unsigned redux_min_u32(unsigned v)
{
    unsigned r;
    asm("redux.sync.min.u32 %0, %1, 0xffffffff;" : "=r"(r) : "r"(v));
    return r;
}

// packed fp32 helpers
#define ADD2(d, a, b) \
    asm("add.rn.f32x2 %0, %1, %2;" : "=l"(d) : "l"(a), "l"(b))
#define UNPK2(lo, hi, v) \
    asm("mov.b64 {%0, %1}, %2;" : "=r"(lo), "=r"(hi) : "l"(v))

// ---------------------------------------------------------------------------
// Kernel 2: Viterbi. One CTA/batch, 512 threads: u = tid>>2, q = tid&3.
// Each thread scans 32 u' (quarter q), chain pairs packed in cpk[16] regs.
// Rotation rot = 8q keeps every LDS.128 conflict-free (q groups hit float
// banks {0,8,16,24}+offset). Static 4-register prefetch ring; combine via
// shfl.xor 1,2. 4 warps/SMSP to hide LDS/shfl/barrier latency.
// ---------------------------------------------------------------------------
#define CHT_LD 132   // 528B rows: 16B-aligned, de-striped STS

__global__ __launch_bounds__(512, 1)
void viterbi_kernel(const float* __restrict__ chain,
                    float* __restrict__ out)
{
    extern __shared__ float sm[];
    float* chT   = sm;                 // [128][CHT_LD]
    float* state = sm + UU * CHT_LD;   // [2][128]

    const int tid  = threadIdx.x;
    const int b    = blockIdx.x;
    const int u    = tid >> 2;         // 0..127
    const int q    = tid & 3;          // u' block [q*32, q*32+32)
    const int base = q * 32;
    const int rot  = 8 * q;            // bank de-rotation offset

    const float* lg = g_logits + (size_t)b * TT * UU;
    float*       hb = g_hist   + (size_t)b * TT * UU;

    // Transposed chain into smem (backtrace)
    for (int i = tid; i < UU * UU; i += 512) {
        const int r = i >> 7, c = i & 127;
        chT[c * CHT_LD + r] = chain[i];
    }

    // chain column, rotated order, packed as f32x2 pairs (u' = e0, e0+1)
    u64 cpk[16];
    #pragma unroll
    for (int k = 0; k < 16; k++) {
        const int e0 = base + ((2 * k + rot) & 31);
        const float c0 = chain[(size_t)e0 * UU + u];
        const float c1 = chain[(size_t)(e0 + 1) * UU + u];
        asm("mov.b64 %0, {%1, %2};" : "=l"(cpk[k])
            : "r"(__float_as_uint(c0)), "r"(__float_as_uint(c1)));
    }

    if (tid < UU)
        state[tid] = lg[tid];

    // prefetch ring: p0..p3 hold logits rows t=1..4 for this u
    float p0 = lg[1 * UU + u];
    float p1 = lg[2 * UU + u];
    float p2 = lg[3 * UU + u];
    float p3 = lg[4 * UU + u];
    const float* pref_ptr = lg + (size_t)5 * UU + u;
    float*       hist_ptr = hb + (size_t)1 * UU + u;

    __syncthreads();

    int cur = 0;

#define VSTEP(T, PREG)                                                       \
    {                                                                        \
        const float pot = PREG;                                              \
        if ((T) + 4 < TT) PREG = *pref_ptr;                                  \
        pref_ptr += UU;                                                      \
        const float* stp = state + cur * UU;                                 \
        float m0 = -INFINITY, m1 = -INFINITY, m2 = -INFINITY, m3 = -INFINITY;\
        float m4 = -INFINITY, m5 = -INFINITY, m6 = -INFINITY, m7 = -INFINITY;\
        _Pragma("unroll")                                                    \
        for (int j = 0; j < 32; j += 8) {                                    \
            const int e = base + ((j + rot) & 31);                           \
            const ulonglong2 sA =                                            \
                *reinterpret_cast<const ulonglong2*>(&stp[e]);               \
            const ulonglong2 sB =                                            \
                *reinterpret_cast<const ulonglong2*>(&stp[e + 4]);           \
            u64 r0, r1, r2, r3;                                              \
            ADD2(r0, sA.x, cpk[(j >> 1) + 0]);                               \
            ADD2(r1, sA.y, cpk[(j >> 1) + 1]);                               \
            ADD2(r2, sB.x, cpk[(j >> 1) + 2]);                               \
            ADD2(r3, sB.y, cpk[(j >> 1) + 3]);                               \
            unsigned x0, x1, x2, x3, x4, x5, x6, x7;                         \
            UNPK2(x0, x1, r0);                                               \
            UNPK2(x2, x3, r1);                                               \
            UNPK2(x4, x5, r2);                                               \
            UNPK2(x6, x7, r3);                                               \
            m0 = fmaxf(m0, __uint_as_float(x0));                             \
            m1 = fmaxf(m1, __uint_as_float(x1));                             \
            m2 = fmaxf(m2, __uint_as_float(x2));                             \
            m3 = fmaxf(m3, __uint_as_float(x3));                             \
            m4 = fmaxf(m4, __uint_as_float(x4));                             \
            m5 = fmaxf(m5, __uint_as_float(x5));                             \
            m6 = fmaxf(m6, __uint_as_float(x6));                             \
            m7 = fmaxf(m7, __uint_as_float(x7));                             \
        }                                                                    \
        float m = fmaxf(fmaxf(fmaxf(m0, m1), fmaxf(m2, m3)),                 \
                        fmaxf(fmaxf(m4, m5), fmaxf(m6, m7)));                \
        m = fmaxf(m, __shfl_xor_sync(0xffffffffu, m, 1));                    \
        m = fmaxf(m, __shfl_xor_sync(0xffffffffu, m, 2));                    \
        const float ns = pot + m;                                            \
        if (q == 0)                                                          \
            state[(cur ^ 1) * UU + u] = ns;                                  \
        else if (q == 1)                                                     \
            *hist_ptr = ns;                                                  \
        hist_ptr += UU;                                                      \
        cur ^= 1;                                                            \
        __syncthreads();                                                     \
    }

    int t = 1;
    for (; t + 3 < TT; t += 4) {
        VSTEP(t + 0, p0);
        VSTEP(t + 1, p1);
        VSTEP(t + 2, p2);
        VSTEP(t + 3, p3);
    }
    // tail: t = 509, 510, 511
    VSTEP(t + 0, p0);
    VSTEP(t + 1, p1);
    VSTEP(t + 2, p2);
#undef VSTEP

    // ---------------- Backtrace: warp 0 only ----------------
    if (tid < 32) {
        const int lane = tid;
        float* o = out + (size_t)b * TT;

        const float4 fs =
            *reinterpret_cast<const float4*>(&state[cur * UU + lane * 4]);
        unsigned k0 = fkey(fs.x), k1 = fkey(fs.y);
        unsigned k2 = fkey(fs.z), k3 = fkey(fs.w);
        unsigned M = redux_max_u32(umax(umax(k0, k1), umax(k2, k3)));
        unsigned idx = 0x7fffffffu;
        if (k3 == M) idx = lane * 4 + 3;
        if (k2 == M) idx = lane * 4 + 2;
        if (k1 == M) idx = lane * 4 + 1;
        if (k0 == M) idx = lane * 4 + 0;
        unsigned tag = redux_min_u32(idx);
        if (lane == 0) o[TT - 1] = (float)tag;

        const float* row_next = hb + (size_t)(TT - 2) * UU;
        float4 sb = *reinterpret_cast<const float4*>(&row_next[lane * 4]);
        for (int tt = TT - 2; tt >= 0; tt--) {
            const float4 sv = sb;
            if (tt > 0) {
                const float* rp =
                    (tt - 1 == 0) ? lg : hb + (size_t)(tt - 1) * UU;
                sb = *reinterpret_cast<const float4*>(&rp[lane * 4]);
            }
            const float4 ch = *reinterpret_cast<const float4*>(
                &chT[tag * CHT_LD + lane * 4]);
            k0 = fkey(sv.x + ch.x);
            k1 = fkey(sv.y + ch.y);
            k2 = fkey(sv.z + ch.z);
            k3 = fkey(sv.w + ch.w);
            M = redux_max_u32(umax(umax(k0, k1), umax(k2, k3)));
            idx = 0x7fffffffu;
            if (k3 == M) idx = lane * 4 + 3;
            if (k2 == M) idx = lane * 4 + 2;
            if (k1 == M) idx = lane * 4 + 1;
            if (k0 == M) idx = lane * 4 + 0;
            tag = redux_min_u32(idx);
            if (lane == 0) o[tt] = (float)tag;
        }
    }
}

// ---------------------------------------------------------------------------
extern "C" void kernel_launch(void* const* d_in, const int* in_sizes, int n_in,
                              void* d_out, int out_size)
{
    const float* inputs = (const float*)d_in[0];   // (B,T,D)
    const float* kernel = (const float*)d_in[1];   // (D,U)
    const float* bias   = (const float*)d_in[2];   // (U)
    const float* chain  = (const float*)d_in[3];   // (U,U)
    float* out = (float*)d_out;                    // (B,T)

    (void)in_sizes; (void)n_in; (void)out_size;

    gemm_bias_kernel<<<MM / GBM, 256>>>(inputs, kernel, bias);

    const int smem_v = (UU * CHT_LD + 2 * UU) * (int)sizeof(float); // 68608
    cudaFuncSetAttribute(viterbi_kernel,
                         cudaFuncAttributeMaxDynamicSharedMemorySize,
                         smem_v);
    viterbi_kernel<<<BB, 512, smem_v>>>(chain, out);
}

// round 13
// speedup vs baseline: 1.1765x; 1.1765x over previous
#include <cuda_runtime.h>
#include <cuda_bf16.h>
#include <math.h>
#include <stdint.h>

// Problem shapes (fixed)
#define BB 64
#define TT 512
#define DD 1024
#define UU 128
#define MM (BB * TT)

typedef unsigned long long u64;

// Scratch (no cudaMalloc allowed)
__device__ float g_logits[MM * UU];   // GEMM output
__device__ float g_hist[MM * UU];     // viterbi state history (t>=1)

// ---------------------------------------------------------------------------
// Kernel 1: logits = X(M,K) @ W(K,U) + bias  (exact fp32, double-buffered)
// ---------------------------------------------------------------------------
#define GBM 128
#define GBK 16

__global__ __launch_bounds__(256, 2)
void gemm_bias_kernel(const float* __restrict__ A,
                      const float* __restrict__ W,
                      const float* __restrict__ bias)
{
    __shared__ float As[2][GBK][GBM];
    __shared__ float Bs[2][GBK][UU];

    const int tid  = threadIdx.x;
    const int row0 = blockIdx.x * GBM;

    const int arow = tid >> 2;
    const int ak   = (tid & 3) * 4;
    const int wk   = tid >> 5;
    const int wcol = (tid & 31) * 4;

    const int tx = tid & 15;
    const int ty = tid >> 4;

    float acc[8][8];
    #pragma unroll
    for (int i = 0; i < 8; i++)
        #pragma unroll
        for (int j = 0; j < 8; j++)
            acc[i][j] = 0.0f;

    const float* A0 = A + (size_t)(row0 + arow) * DD + ak;
    const float* A1 = A + (size_t)(row0 + arow + 64) * DD + ak;

    float4 ra0 = *reinterpret_cast<const float4*>(A0);
    float4 ra1 = *reinterpret_cast<const float4*>(A1);
    float4 rw0 = *reinterpret_cast<const float4*>(&W[(size_t)wk * UU + wcol]);
    float4 rw1 = *reinterpret_cast<const float4*>(&W[(size_t)(wk + 8) * UU + wcol]);

    As[0][ak + 0][arow] = ra0.x; As[0][ak + 1][arow] = ra0.y;
    As[0][ak + 2][arow] = ra0.z; As[0][ak + 3][arow] = ra0.w;
    As[0][ak + 0][arow + 64] = ra1.x; As[0][ak + 1][arow + 64] = ra1.y;
    As[0][ak + 2][arow + 64] = ra1.z; As[0][ak + 3][arow + 64] = ra1.w;
    *reinterpret_cast<float4*>(&Bs[0][wk][wcol])     = rw0;
    *reinterpret_cast<float4*>(&Bs[0][wk + 8][wcol]) = rw1;
    __syncthreads();

    int st = 0;
    for (int k0 = GBK; k0 <= DD; k0 += GBK) {
        const bool more = (k0 < DD);
        if (more) {
            ra0 = *reinterpret_cast<const float4*>(A0 + k0);
            ra1 = *reinterpret_cast<const float4*>(A1 + k0);
            rw0 = *reinterpret_cast<const float4*>(&W[(size_t)(k0 + wk) * UU + wcol]);
            rw1 = *reinterpret_cast<const float4*>(&W[(size_t)(k0 + wk + 8) * UU + wcol]);
        }

        #pragma unroll
        for (int k = 0; k < GBK; k++) {
            float a[8], b[8];
            *reinterpret_cast<float4*>(&a[0]) =
                *reinterpret_cast<const float4*>(&As[st][k][ty * 8]);
            *reinterpret_cast<float4*>(&a[4]) =
                *reinterpret_cast<const float4*>(&As[st][k][ty * 8 + 4]);
            *reinterpret_cast<float4*>(&b[0]) =
                *reinterpret_cast<const float4*>(&Bs[st][k][tx * 8]);
            *reinterpret_cast<float4*>(&b[4]) =
                *reinterpret_cast<const float4*>(&Bs[st][k][tx * 8 + 4]);
            #pragma unroll
            for (int i = 0; i < 8; i++)
                #pragma unroll
                for (int j = 0; j < 8; j++)
                    acc[i][j] = fmaf(a[i], b[j], acc[i][j]);
        }

        if (more) {
            const int ns = st ^ 1;
            As[ns][ak + 0][arow] = ra0.x; As[ns][ak + 1][arow] = ra0.y;
            As[ns][ak + 2][arow] = ra0.z; As[ns][ak + 3][arow] = ra0.w;
            As[ns][ak + 0][arow + 64] = ra1.x; As[ns][ak + 1][arow + 64] = ra1.y;
            As[ns][ak + 2][arow + 64] = ra1.z; As[ns][ak + 3][arow + 64] = ra1.w;
            *reinterpret_cast<float4*>(&Bs[ns][wk][wcol])     = rw0;
            *reinterpret_cast<float4*>(&Bs[ns][wk + 8][wcol]) = rw1;
            __syncthreads();
            st = ns;
        }
    }

    float bv[8];
    *reinterpret_cast<float4*>(&bv[0]) =
        *reinterpret_cast<const float4*>(&bias[tx * 8]);
    *reinterpret_cast<float4*>(&bv[4]) =
        *reinterpret_cast<const float4*>(&bias[tx * 8 + 4]);

    #pragma unroll
    for (int i = 0; i < 8; i++) {
        const size_t row = (size_t)(row0 + ty * 8 + i);
        float4 o0, o1;
        o0.x = acc[i][0] + bv[0]; o0.y = acc[i][1] + bv[1];
        o0.z = acc[i][2] + bv[2]; o0.w = acc[i][3] + bv[3];
        o1.x = acc[i][4] + bv[4]; o1.y = acc[i][5] + bv[5];
        o1.z = acc[i][6] + bv[6]; o1.w = acc[i][7] + bv[7];
        *reinterpret_cast<float4*>(&g_logits[row * UU + tx * 8])     = o0;
        *reinterpret_cast<float4*>(&g_logits[row * UU + tx * 8 + 4]) = o1;
    }
}

// ---------------------------------------------------------------------------
// ordered-int argmax helpers (exact, first-index tie rule)
// ---------------------------------------------------------------------------
__device__ __forceinline__ unsigned fkey(float f)
{
    const unsigned b = __float_as_uint(f);
    return b ^ ((unsigned)(((int)b) >> 31) | 0x80000000u);
}
__device__ __forceinline__ unsigned redux_max_u32(unsigned v)
{
    unsigned r;
    asm("redux.sync.max.u32 %0, %1, 0xffffffff;" : "=r"(r) : "r"(v));
    return r;
}
__device__ __forceinline__ unsigned redux_min_u32(unsigned v)
{
    unsigned r;
    asm("redux.sync.min.u32 %0, %1, 0xffffffff;" : "=r"(r) : "r"(v));
    return r;
}

// packed fp32 helpers
#define ADD2(d, a, b) \
    asm("add.rn.f32x2 %0, %1, %2;" : "=l"(d) : "l"(a), "l"(b))
#define UNPK2(lo, hi, v) \
    asm("mov.b64 {%0, %1}, %2;" : "=r"(lo), "=r"(hi) : "l"(v))

// ---------------------------------------------------------------------------
// Kernel 2: Viterbi. One CTA/batch, 128 threads, thread = state u.
// Each thread scans ALL 128 u' with its chain column packed in cpk[64] regs.
// State reads are warp-broadcast LDS (conflict-free). No shuffles, no work
// division: 16 private max accumulators + tree. One 4-warp barrier per step.
// ---------------------------------------------------------------------------
#define CHT_LD 132   // 528B rows: 16B-aligned, de-striped STS

__global__ __launch_bounds__(128, 1)
void viterbi_kernel(const float* __restrict__ chain,
                    float* __restrict__ out)
{
    extern __shared__ float sm[];
    float* chT   = sm;                 // [128][CHT_LD]
    float* state = sm + UU * CHT_LD;   // [2][128]

    const int tid = threadIdx.x;       // = u, 0..127
    const int b   = blockIdx.x;
    const int u   = tid;

    const float* lg = g_logits + (size_t)b * TT * UU;
    float*       hb = g_hist   + (size_t)b * TT * UU;

    // Transposed chain into smem (backtrace)
    for (int i = tid; i < UU * UU; i += 128) {
        const int r = i >> 7, c = i & 127;
        chT[c * CHT_LD + r] = chain[i];
    }

    // full chain column for this u, packed as f32x2 pairs: cpk[k] = (C[2k][u], C[2k+1][u])
    u64 cpk[64];
    #pragma unroll
    for (int k = 0; k < 64; k++) {
        const float c0 = chain[(size_t)(2 * k)     * UU + u];
        const float c1 = chain[(size_t)(2 * k + 1) * UU + u];
        asm("mov.b64 %0, {%1, %2};" : "=l"(cpk[k])
            : "r"(__float_as_uint(c0)), "r"(__float_as_uint(c1)));
    }

    state[tid] = lg[tid];

    // prefetch ring: p0..p3 hold logits rows t=1..4 for this u
    float p0 = lg[1 * UU + u];
    float p1 = lg[2 * UU + u];
    float p2 = lg[3 * UU + u];
    float p3 = lg[4 * UU + u];
    const float* pref_ptr = lg + (size_t)5 * UU + u;
    float*       hist_ptr = hb + (size_t)1 * UU + u;

    __syncthreads();

    int cur = 0;

#define VSTEP(T, PREG)                                                       \
    {                                                                        \
        const float pot = PREG;                                              \
        if ((T) + 4 < TT) PREG = *pref_ptr;                                  \
        pref_ptr += UU;                                                      \
        const float* stp = state + cur * UU;                                 \
        float ma0 = -INFINITY, ma1 = -INFINITY, ma2 = -INFINITY,             \
              ma3 = -INFINITY, ma4 = -INFINITY, ma5 = -INFINITY,             \
              ma6 = -INFINITY, ma7 = -INFINITY;                              \
        float mb0 = -INFINITY, mb1 = -INFINITY, mb2 = -INFINITY,             \
              mb3 = -INFINITY, mb4 = -INFINITY, mb5 = -INFINITY,             \
              mb6 = -INFINITY, mb7 = -INFINITY;                              \
        _Pragma("unroll")                                                    \
        for (int j = 0; j < 128; j += 16) {                                  \
            const ulonglong2 sA =                                            \
                *reinterpret_cast<const ulonglong2*>(&stp[j]);               \
            const ulonglong2 sB =                                            \
                *reinterpret_cast<const ulonglong2*>(&stp[j + 4]);           \
            const ulonglong2 sC =                                            \
                *reinterpret_cast<const ulonglong2*>(&stp[j + 8]);           \
            const ulonglong2 sD =                                            \
                *reinterpret_cast<const ulonglong2*>(&stp[j + 12]);          \
            u64 r0, r1, r2, r3, r4, r5, r6, r7;                              \
            ADD2(r0, sA.x, cpk[(j >> 1) + 0]);                               \
            ADD2(r1, sA.y, cpk[(j >> 1) + 1]);                               \
            ADD2(r2, sB.x, cpk[(j >> 1) + 2]);                               \
            ADD2(r3, sB.y, cpk[(j >> 1) + 3]);                               \
            ADD2(r4, sC.x, cpk[(j >> 1) + 4]);                               \
            ADD2(r5, sC.y, cpk[(j >> 1) + 5]);                               \
            ADD2(r6, sD.x, cpk[(j >> 1) + 6]);                               \
            ADD2(r7, sD.y, cpk[(j >> 1) + 7]);                               \
            unsigned x0, x1, x2, x3, x4, x5, x6, x7;                         \
            unsigned y0, y1, y2, y3, y4, y5, y6, y7;                         \
            UNPK2(x0, x1, r0);                                               \
            UNPK2(x2, x3, r1);                                               \
            UNPK2(x4, x5, r2);                                               \
            UNPK2(x6, x7, r3);                                               \
            UNPK2(y0, y1, r4);                                               \
            UNPK2(y2, y3, r5);                                               \
            UNPK2(y4, y5, r6);                                               \
            UNPK2(y6, y7, r7);                                               \
            ma0 = fmaxf(ma0, __uint_as_float(x0));                           \
            ma1 = fmaxf(ma1, __uint_as_float(x1));                           \
            ma2 = fmaxf(ma2, __uint_as_float(x2));                           \
            ma3 = fmaxf(ma3, __uint_as_float(x3));                           \
            ma4 = fmaxf(ma4, __uint_as_float(x4));                           \
            ma5 = fmaxf(ma5, __uint_as_float(x5));                           \
            ma6 = fmaxf(ma6, __uint_as_float(x6));                           \
            ma7 = fmaxf(ma7, __uint_as_float(x7));                           \
            mb0 = fmaxf(mb0, __uint_as_float(y0));                           \
            mb1 = fmaxf(mb1, __uint_as_float(y1));                           \
            mb2 = fmaxf(mb2, __uint_as_float(y2));                           \
            mb3 = fmaxf(mb3, __uint_as_float(y3));                           \
            mb4 = fmaxf(mb4, __uint_as_float(y4));                           \
            mb5 = fmaxf(mb5, __uint_as_float(y5));                           \
            mb6 = fmaxf(mb6, __uint_as_float(y6));                           \
            mb7 = fmaxf(mb7, __uint_as_float(y7));                           \
        }                                                                    \
        const float mA = fmaxf(fmaxf(fmaxf(ma0, ma1), fmaxf(ma2, ma3)),      \
                               fmaxf(fmaxf(ma4, ma5), fmaxf(ma6, ma7)));     \
        const float mB = fmaxf(fmaxf(fmaxf(mb0, mb1), fmaxf(mb2, mb3)),      \
                               fmaxf(fmaxf(mb4, mb5), fmaxf(mb6, mb7)));     \
        const float ns = pot + fmaxf(mA, mB);                                \
        state[(cur ^ 1) * UU + u] = ns;                                      \
        *hist_ptr = ns;                                                      \
        hist_ptr += UU;                                                      \
        cur ^= 1;                                                            \
        __syncthreads();                                                     \
    }

    int t = 1;
    for (; t + 3 < TT; t += 4) {
        VSTEP(t + 0, p0);
        VSTEP(t + 1, p1);
        VSTEP(t + 2, p2);
        VSTEP(t + 3, p3);
    }
    // tail: t = 509, 510, 511
    VSTEP(t + 0, p0);
    VSTEP(t + 1, p1);
    VSTEP(t + 2, p2);
#undef VSTEP

    // ---------------- Backtrace: warp 0 only ----------------
    if (tid < 32) {
        const int lane = tid;
        float* o = out + (size_t)b * TT;

        const float4 fs =
            *reinterpret_cast<const float4*>(&state[cur * UU + lane * 4]);
        unsigned k0 = fkey(fs.x), k1 = fkey(fs.y);
        unsigned k2 = fkey(fs.z), k3 = fkey(fs.w);
        unsigned M = redux_max_u32(umax(umax(k0, k1), umax(k2, k3)));
        unsigned idx = 0x7fffffffu;
        if (k3 == M) idx = lane * 4 + 3;
        if (k2 == M) idx = lane * 4 + 2;
        if (k1 == M) idx = lane * 4 + 1;
        if (k0 == M) idx = lane * 4 + 0;
        unsigned tag = redux_min_u32(idx);
        if (lane == 0) o[TT - 1] = (float)tag;

        const float* row_next = hb + (size_t)(TT - 2) * UU;
        float4 sb = *reinterpret_cast<const float4*>(&row_next[lane * 4]);
        for (int tt = TT - 2; tt >= 0; tt--) {
            const float4 sv = sb;
            if (tt > 0) {
                const float* rp =
                    (tt - 1 == 0) ? lg : hb + (size_t)(tt - 1) * UU;
                sb = *reinterpret_cast<const float4*>(&rp[lane * 4]);
            }
            const float4 ch = *reinterpret_cast<const float4*>(
                &chT[tag * CHT_LD + lane * 4]);
            k0 = fkey(sv.x + ch.x);
            k1 = fkey(sv.y + ch.y);
            k2 = fkey(sv.z + ch.z);
            k3 = fkey(sv.w + ch.w);
            M = redux_max_u32(umax(umax(k0, k1), umax(k2, k3)));
            idx = 0x7fffffffu;
            if (k3 == M) idx = lane * 4 + 3;
            if (k2 == M) idx = lane * 4 + 2;
            if (k1 == M) idx = lane * 4 + 1;
            if (k0 == M) idx = lane * 4 + 0;
            tag = redux_min_u32(idx);
            if (lane == 0) o[tt] = (float)tag;
        }
    }
}

// ---------------------------------------------------------------------------
extern "C" void kernel_launch(void* const* d_in, const int* in_sizes, int n_in,
                              void* d_out, int out_size)
{
    const float* inputs = (const float*)d_in[0];   // (B,T,D)
    const float* kernel = (const float*)d_in[1];   // (D,U)
    const float* bias   = (const float*)d_in[2];   // (U)
    const float* chain  = (const float*)d_in[3];   // (U,U)
    float* out = (float*)d_out;                    // (B,T)

    (void)in_sizes; (void)n_in; (void)out_size;

    gemm_bias_kernel<<<MM / GBM, 256>>>(inputs, kernel, bias);

    const int smem_v = (UU * CHT_LD + 2 * UU) * (int)sizeof(float); // 68608
    cudaFuncSetAttribute(viterbi_kernel,
                         cudaFuncAttributeMaxDynamicSharedMemorySize,
                         smem_v);
    viterbi_kernel<<<BB, 128, smem_v>>>(chain, out);
}